// round 1
// baseline (speedup 1.0000x reference)
#include <cuda_runtime.h>
#include <cuda_bf16.h>
#include <math.h>

#define D_MODEL 1024
#define NH 16
#define HD 64
#define BATCH 2
#define SEQ 2048
#define MROWS (BATCH*SEQ)

// Scratch: q,k,v in [B,H,S,HD], ctx in [B*S, D_MODEL]
__device__ float g_q[BATCH*NH*SEQ*HD];
__device__ float g_k[BATCH*NH*SEQ*HD];
__device__ float g_v[BATCH*NH*SEQ*HD];
__device__ float g_ctx[MROWS*D_MODEL];

__device__ __forceinline__ unsigned f2tf(float x) {
    unsigned r;
    asm("cvt.rna.tf32.f32 %0, %1;" : "=r"(r) : "f"(x));
    return r;
}

__device__ __forceinline__ void mma8(float* c, const unsigned* a, const unsigned* b) {
    asm volatile(
        "mma.sync.aligned.m16n8k8.row.col.f32.tf32.tf32.f32 "
        "{%0,%1,%2,%3}, {%4,%5,%6,%7}, {%8,%9}, {%0,%1,%2,%3};"
        : "+f"(c[0]), "+f"(c[1]), "+f"(c[2]), "+f"(c[3])
        : "r"(a[0]), "r"(a[1]), "r"(a[2]), "r"(a[3]), "r"(b[0]), "r"(b[1]));
}

// ============================================================================
// TF32 GEMM: Y = X @ W^T.  X [M,1024] row-major, W [N,K]=[1024,1024] row-major.
// proj_mode=1: scatter Y[m, n=h*64+d] -> dst[((b*NH+h)*SEQ+s)*HD + d]
// proj_mode=0: plain Y[m*D_MODEL + n]
// ============================================================================
#define GBM 128
#define GBN 128
#define GBK 32
#define GST 36   // padded smem stride: bank = (4*m + k) % 32 -> conflict-free frags

__global__ __launch_bounds__(256) void gemm_tf32(
    const float* __restrict__ X, const float* __restrict__ W,
    float* __restrict__ Y, int proj_mode)
{
    __shared__ unsigned As[GBM*GST];
    __shared__ unsigned Bs[GBN*GST];
    const int tid = threadIdx.x;
    const int wid = tid >> 5, lane = tid & 31;
    const int g = lane >> 2, tq = lane & 3;
    const int wm = wid & 1, wn = wid >> 1;          // 2 x 4 warp grid
    const int bm = blockIdx.y * GBM, bn = blockIdx.x * GBN;

    float acc[4][4][4];
    #pragma unroll
    for (int i = 0; i < 4; i++)
        #pragma unroll
        for (int j = 0; j < 4; j++)
            #pragma unroll
            for (int r = 0; r < 4; r++) acc[i][j][r] = 0.f;

    for (int kt = 0; kt < D_MODEL; kt += GBK) {
        #pragma unroll
        for (int i = 0; i < 4; i++) {
            int idx = tid + i * 256;
            int r = idx >> 3;
            int c4 = (idx & 7) << 2;
            float4 va = *(const float4*)(X + (size_t)(bm + r) * D_MODEL + kt + c4);
            unsigned* da = As + r * GST + c4;
            da[0] = f2tf(va.x); da[1] = f2tf(va.y); da[2] = f2tf(va.z); da[3] = f2tf(va.w);
            float4 vb = *(const float4*)(W + (size_t)(bn + r) * D_MODEL + kt + c4);
            unsigned* db = Bs + r * GST + c4;
            db[0] = f2tf(vb.x); db[1] = f2tf(vb.y); db[2] = f2tf(vb.z); db[3] = f2tf(vb.w);
        }
        __syncthreads();
        #pragma unroll
        for (int kk = 0; kk < GBK; kk += 8) {
            unsigned af[4][4];
            unsigned bf[4][2];
            #pragma unroll
            for (int mt = 0; mt < 4; mt++) {
                int row = wm * 64 + mt * 16 + g;
                af[mt][0] = As[row * GST + kk + tq];
                af[mt][1] = As[(row + 8) * GST + kk + tq];
                af[mt][2] = As[row * GST + kk + tq + 4];
                af[mt][3] = As[(row + 8) * GST + kk + tq + 4];
            }
            #pragma unroll
            for (int nt = 0; nt < 4; nt++) {
                int col = wn * 32 + nt * 8 + g;
                bf[nt][0] = Bs[col * GST + kk + tq];
                bf[nt][1] = Bs[col * GST + kk + tq + 4];
            }
            #pragma unroll
            for (int mt = 0; mt < 4; mt++)
                #pragma unroll
                for (int nt = 0; nt < 4; nt++)
                    mma8(acc[mt][nt], af[mt], bf[nt]);
        }
        __syncthreads();
    }

    // epilogue
    #pragma unroll
    for (int mt = 0; mt < 4; mt++) {
        #pragma unroll
        for (int nt = 0; nt < 4; nt++) {
            int row0 = bm + wm * 64 + mt * 16 + g;
            int col = bn + wn * 32 + nt * 8 + tq * 2;
            #pragma unroll
            for (int half = 0; half < 2; half++) {
                int row = row0 + half * 8;
                float v0 = acc[mt][nt][half * 2 + 0];
                float v1 = acc[mt][nt][half * 2 + 1];
                if (proj_mode) {
                    int b = row / SEQ, s = row % SEQ;   // powers of 2 -> shifts
                    int hh = col / HD, d = col % HD;
                    float* dst = Y + ((size_t)((b * NH + hh) * SEQ + s)) * HD + d;
                    dst[0] = v0; dst[1] = v1;
                } else {
                    float* dst = Y + (size_t)row * D_MODEL + col;
                    dst[0] = v0; dst[1] = v1;
                }
            }
        }
    }
}

// ============================================================================
// Causal flash attention, TF32 MMA. One block = 64 q-rows of one (b,h).
// 4 warps; warp w owns rows [16w, 16w+16). smem stride 72 -> conflict-free
// for both A-pattern (8m+k) and V B-pattern loads.
// ============================================================================
#define FST 72
#define FTS 64
#define FSMEM (3 * FTS * FST * 4)

__global__ __launch_bounds__(128) void flash_kernel()
{
    extern __shared__ unsigned smf[];
    unsigned* Qs = smf;
    unsigned* Ks = smf + FTS * FST;   // reused as P after scores
    unsigned* Vs = smf + 2 * FTS * FST;

    const int tid = threadIdx.x;
    const int w = tid >> 5, lane = tid & 31;
    const int g = lane >> 2, tq = lane & 3;
    const int bh = blockIdx.y;
    const int b = bh / NH, h = bh % NH;
    const int qt = blockIdx.x;
    const int q0 = qt * FTS;

    const float* qbase = g_q + (size_t)(b * NH + h) * SEQ * HD;
    const float* kbase = g_k + (size_t)(b * NH + h) * SEQ * HD;
    const float* vbase = g_v + (size_t)(b * NH + h) * SEQ * HD;

    // load Q tile (64x64)
    #pragma unroll
    for (int i = 0; i < 8; i++) {
        int idx = tid + i * 128;
        int r = idx >> 4, c4 = (idx & 15) << 2;
        float4 vq = *(const float4*)(qbase + (size_t)(q0 + r) * HD + c4);
        unsigned* dq = Qs + r * FST + c4;
        dq[0] = f2tf(vq.x); dq[1] = f2tf(vq.y); dq[2] = f2tf(vq.z); dq[3] = f2tf(vq.w);
    }

    float o[8][4];
    #pragma unroll
    for (int nt = 0; nt < 8; nt++)
        #pragma unroll
        for (int r = 0; r < 4; r++) o[nt][r] = 0.f;
    float m0 = -INFINITY, m1 = -INFINITY, l0 = 0.f, l1 = 0.f;

    const int row0g = q0 + w * 16 + g;   // global seq row of c0/c1
    const int row1g = row0g + 8;         // global seq row of c2/c3
    const int prow = w * 16 + g;         // tile-local

    for (int kt = 0; kt <= qt; kt++) {
        const int kv0 = kt * FTS;
        // load K, V tiles
        #pragma unroll
        for (int i = 0; i < 8; i++) {
            int idx = tid + i * 128;
            int r = idx >> 4, c4 = (idx & 15) << 2;
            float4 vk = *(const float4*)(kbase + (size_t)(kv0 + r) * HD + c4);
            unsigned* dk = Ks + r * FST + c4;
            dk[0] = f2tf(vk.x); dk[1] = f2tf(vk.y); dk[2] = f2tf(vk.z); dk[3] = f2tf(vk.w);
            float4 vv = *(const float4*)(vbase + (size_t)(kv0 + r) * HD + c4);
            unsigned* dv = Vs + r * FST + c4;
            dv[0] = f2tf(vv.x); dv[1] = f2tf(vv.y); dv[2] = f2tf(vv.z); dv[3] = f2tf(vv.w);
        }
        __syncthreads();

        // scores S = Q K^T (16 rows x 64 cols per warp)
        float sc[8][4];
        #pragma unroll
        for (int nt = 0; nt < 8; nt++)
            #pragma unroll
            for (int r = 0; r < 4; r++) sc[nt][r] = 0.f;
        #pragma unroll
        for (int kk = 0; kk < HD; kk += 8) {
            unsigned af[4];
            af[0] = Qs[prow * FST + kk + tq];
            af[1] = Qs[(prow + 8) * FST + kk + tq];
            af[2] = Qs[prow * FST + kk + tq + 4];
            af[3] = Qs[(prow + 8) * FST + kk + tq + 4];
            #pragma unroll
            for (int nt = 0; nt < 8; nt++) {
                unsigned bf[2];
                int col = nt * 8 + g;
                bf[0] = Ks[col * FST + kk + tq];
                bf[1] = Ks[col * FST + kk + tq + 4];
                mma8(sc[nt], af, bf);
            }
        }

        // scale + causal mask (only diagonal tile needs masking)
        const bool diag = (kt == qt);
        #pragma unroll
        for (int nt = 0; nt < 8; nt++) {
            #pragma unroll
            for (int r = 0; r < 4; r++) sc[nt][r] *= 0.125f;
            if (diag) {
                int c0 = kv0 + nt * 8 + tq * 2;
                if (c0     > row0g) sc[nt][0] = -1e30f;
                if (c0 + 1 > row0g) sc[nt][1] = -1e30f;
                if (c0     > row1g) sc[nt][2] = -1e30f;
                if (c0 + 1 > row1g) sc[nt][3] = -1e30f;
            }
        }

        // online softmax
        float rm0 = -1e30f, rm1 = -1e30f;
        #pragma unroll
        for (int nt = 0; nt < 8; nt++) {
            rm0 = fmaxf(rm0, fmaxf(sc[nt][0], sc[nt][1]));
            rm1 = fmaxf(rm1, fmaxf(sc[nt][2], sc[nt][3]));
        }
        rm0 = fmaxf(rm0, __shfl_xor_sync(0xffffffffu, rm0, 1));
        rm0 = fmaxf(rm0, __shfl_xor_sync(0xffffffffu, rm0, 2));
        rm1 = fmaxf(rm1, __shfl_xor_sync(0xffffffffu, rm1, 1));
        rm1 = fmaxf(rm1, __shfl_xor_sync(0xffffffffu, rm1, 2));

        float nm0 = fmaxf(m0, rm0), nm1 = fmaxf(m1, rm1);
        float a0 = __expf(m0 - nm0), a1 = __expf(m1 - nm1);
        m0 = nm0; m1 = nm1;

        float rs0 = 0.f, rs1 = 0.f;
        #pragma unroll
        for (int nt = 0; nt < 8; nt++) {
            float p0 = __expf(sc[nt][0] - nm0); sc[nt][0] = p0; rs0 += p0;
            float p1 = __expf(sc[nt][1] - nm0); sc[nt][1] = p1; rs0 += p1;
            float p2 = __expf(sc[nt][2] - nm1); sc[nt][2] = p2; rs1 += p2;
            float p3 = __expf(sc[nt][3] - nm1); sc[nt][3] = p3; rs1 += p3;
        }
        rs0 += __shfl_xor_sync(0xffffffffu, rs0, 1);
        rs0 += __shfl_xor_sync(0xffffffffu, rs0, 2);
        rs1 += __shfl_xor_sync(0xffffffffu, rs1, 1);
        rs1 += __shfl_xor_sync(0xffffffffu, rs1, 2);
        l0 = l0 * a0 + rs0;
        l1 = l1 * a1 + rs1;

        #pragma unroll
        for (int nt = 0; nt < 8; nt++) {
            o[nt][0] *= a0; o[nt][1] *= a0;
            o[nt][2] *= a1; o[nt][3] *= a1;
        }

        __syncthreads();   // all warps done reading Ks as K
        // write P (C-layout -> smem) into Ks buffer
        #pragma unroll
        for (int nt = 0; nt < 8; nt++) {
            int c = nt * 8 + tq * 2;
            Ks[prow * FST + c]           = f2tf(sc[nt][0]);
            Ks[prow * FST + c + 1]       = f2tf(sc[nt][1]);
            Ks[(prow + 8) * FST + c]     = f2tf(sc[nt][2]);
            Ks[(prow + 8) * FST + c + 1] = f2tf(sc[nt][3]);
        }
        __syncthreads();

        // O += P V  (A = P from smem, B = V: b[k][n] = Vs[kv][d])
        #pragma unroll
        for (int kk = 0; kk < FTS; kk += 8) {
            unsigned af[4];
            af[0] = Ks[prow * FST + kk + tq];
            af[1] = Ks[(prow + 8) * FST + kk + tq];
            af[2] = Ks[prow * FST + kk + tq + 4];
            af[3] = Ks[(prow + 8) * FST + kk + tq + 4];
            #pragma unroll
            for (int nt = 0; nt < 8; nt++) {
                unsigned bf[2];
                int col = nt * 8 + g;
                bf[0] = Vs[(kk + tq) * FST + col];
                bf[1] = Vs[(kk + tq + 4) * FST + col];
                mma8(o[nt], af, bf);
            }
        }
        __syncthreads();   // protect Ks/Vs before next iteration's loads
    }

    // epilogue: normalize, write ctx[b*S + row][h*64 + d]
    float inv0 = 1.f / l0, inv1 = 1.f / l1;
    #pragma unroll
    for (int nt = 0; nt < 8; nt++) {
        int colg = h * HD + nt * 8 + tq * 2;
        size_t r0 = (size_t)(b * SEQ + row0g) * D_MODEL + colg;
        size_t r1 = (size_t)(b * SEQ + row1g) * D_MODEL + colg;
        g_ctx[r0]     = o[nt][0] * inv0;
        g_ctx[r0 + 1] = o[nt][1] * inv0;
        g_ctx[r1]     = o[nt][2] * inv1;
        g_ctx[r1 + 1] = o[nt][3] * inv1;
    }
}

// ============================================================================
extern "C" void kernel_launch(void* const* d_in, const int* in_sizes, int n_in,
                              void* d_out, int out_size)
{
    const float* x  = (const float*)d_in[0];
    const float* qW = (const float*)d_in[1];
    const float* kW = (const float*)d_in[2];
    const float* vW = (const float*)d_in[3];
    const float* oW = (const float*)d_in[4];
    float* out = (float*)d_out;

    float *pq, *pk, *pv, *pctx;
    cudaGetSymbolAddress((void**)&pq, g_q);
    cudaGetSymbolAddress((void**)&pk, g_k);
    cudaGetSymbolAddress((void**)&pv, g_v);
    cudaGetSymbolAddress((void**)&pctx, g_ctx);

    cudaFuncSetAttribute(flash_kernel, cudaFuncAttributeMaxDynamicSharedMemorySize, FSMEM);

    dim3 ggrid(D_MODEL / GBN, MROWS / GBM);   // (8, 32)
    gemm_tf32<<<ggrid, 256>>>(x, qW, pq, 1);
    gemm_tf32<<<ggrid, 256>>>(x, kW, pk, 1);
    gemm_tf32<<<ggrid, 256>>>(x, vW, pv, 1);

    flash_kernel<<<dim3(SEQ / FTS, BATCH * NH), 128, FSMEM>>>();

    gemm_tf32<<<ggrid, 256>>>(pctx, oW, out, 0);
}

// round 2
// speedup vs baseline: 1.1031x; 1.1031x over previous
#include <cuda_runtime.h>
#include <cuda_bf16.h>
#include <math.h>

#define D_MODEL 1024
#define NH 16
#define HD 64
#define BATCH 2
#define SEQ 2048
#define MROWS (BATCH*SEQ)

// Scratch: q,k,v in [B,H,S,HD], ctx in [B*S, D_MODEL]
__device__ float g_q[BATCH*NH*SEQ*HD];
__device__ float g_k[BATCH*NH*SEQ*HD];
__device__ float g_v[BATCH*NH*SEQ*HD];
__device__ float g_ctx[MROWS*D_MODEL];

__device__ __forceinline__ unsigned f2tf(float x) {
    unsigned r;
    asm("cvt.rna.tf32.f32 %0, %1;" : "=r"(r) : "f"(x));
    return r;
}

__device__ __forceinline__ void mma8(float* c, const unsigned* a, const unsigned* b) {
    asm volatile(
        "mma.sync.aligned.m16n8k8.row.col.f32.tf32.tf32.f32 "
        "{%0,%1,%2,%3}, {%4,%5,%6,%7}, {%8,%9}, {%0,%1,%2,%3};"
        : "+f"(c[0]), "+f"(c[1]), "+f"(c[2]), "+f"(c[3])
        : "r"(a[0]), "r"(a[1]), "r"(a[2]), "r"(a[3]), "r"(b[0]), "r"(b[1]));
}

__device__ __forceinline__ void cpa16(void* dst_smem, const void* src) {
    unsigned d = (unsigned)__cvta_generic_to_shared(dst_smem);
    asm volatile("cp.async.cg.shared.global [%0], [%1], 16;\n" :: "r"(d), "l"(src));
}

// ============================================================================
// TF32 GEMM, cp.async double-buffered: Y = X @ W^T.
// X [M,1024] row-major, W [N,K]=[1024,1024] row-major.
// proj_mode=1: scatter Y[m, n=h*64+d] -> dst[((b*NH+h)*SEQ+s)*HD + d]
// proj_mode=0: plain Y[m*D_MODEL + n]
// ============================================================================
#define GBM 128
#define GBN 128
#define GBK 32
#define GST 36   // (4g+tq) mod 32 distinct -> conflict-free fragment loads
#define GBUF (GBM*GST)
#define GSMEM (4 * GBUF * 4)   // As[2] + Bs[2], floats

__global__ __launch_bounds__(256) void gemm_tf32(
    const float* __restrict__ X, const float* __restrict__ W,
    float* __restrict__ Y, int proj_mode)
{
    extern __shared__ float gsm[];
    float* As = gsm;            // [2][GBUF]
    float* Bs = gsm + 2*GBUF;   // [2][GBUF]
    const int tid = threadIdx.x;
    const int wid = tid >> 5, lane = tid & 31;
    const int g = lane >> 2, tq = lane & 3;
    const int wm = wid & 1, wn = wid >> 1;          // 2 x 4 warp grid
    const int bm = blockIdx.y * GBM, bn = blockIdx.x * GBN;

    float acc[4][4][4];
    #pragma unroll
    for (int i = 0; i < 4; i++)
        #pragma unroll
        for (int j = 0; j < 4; j++)
            #pragma unroll
            for (int r = 0; r < 4; r++) acc[i][j][r] = 0.f;

    const int lr = tid >> 3;            // 0..31 row index within 128-row tile? no:
    // loader mapping: idx = tid + i*256 -> r = idx>>3 (0..127), c4 = (idx&7)*4 (0..28)
    auto stage = [&](int kt, int buf) {
        float* a = As + buf * GBUF;
        float* b = Bs + buf * GBUF;
        #pragma unroll
        for (int i = 0; i < 4; i++) {
            int idx = tid + i * 256;
            int r = idx >> 3, c4 = (idx & 7) << 2;
            cpa16(a + r * GST + c4, X + (size_t)(bm + r) * D_MODEL + kt + c4);
            cpa16(b + r * GST + c4, W + (size_t)(bn + r) * D_MODEL + kt + c4);
        }
        asm volatile("cp.async.commit_group;\n");
    };

    stage(0, 0);
    const int NS = D_MODEL / GBK;   // 32
    for (int s = 0; s < NS; s++) {
        const int buf = s & 1;
        if (s + 1 < NS) {
            stage((s + 1) * GBK, buf ^ 1);
            asm volatile("cp.async.wait_group 1;\n");
        } else {
            asm volatile("cp.async.wait_group 0;\n");
        }
        __syncthreads();

        const float* a = As + buf * GBUF;
        const float* b = Bs + buf * GBUF;
        #pragma unroll
        for (int kk = 0; kk < GBK; kk += 8) {
            unsigned af[4][4];
            unsigned bf[4][2];
            #pragma unroll
            for (int mt = 0; mt < 4; mt++) {
                int row = wm * 64 + mt * 16 + g;
                af[mt][0] = f2tf(a[row * GST + kk + tq]);
                af[mt][1] = f2tf(a[(row + 8) * GST + kk + tq]);
                af[mt][2] = f2tf(a[row * GST + kk + tq + 4]);
                af[mt][3] = f2tf(a[(row + 8) * GST + kk + tq + 4]);
            }
            #pragma unroll
            for (int nt = 0; nt < 4; nt++) {
                int col = wn * 32 + nt * 8 + g;
                bf[nt][0] = f2tf(b[col * GST + kk + tq]);
                bf[nt][1] = f2tf(b[col * GST + kk + tq + 4]);
            }
            #pragma unroll
            for (int mt = 0; mt < 4; mt++)
                #pragma unroll
                for (int nt = 0; nt < 4; nt++)
                    mma8(acc[mt][nt], af[mt], bf[nt]);
        }
        __syncthreads();
    }

    // epilogue
    #pragma unroll
    for (int mt = 0; mt < 4; mt++) {
        #pragma unroll
        for (int nt = 0; nt < 4; nt++) {
            int row0 = bm + wm * 64 + mt * 16 + g;
            int col = bn + wn * 32 + nt * 8 + tq * 2;
            #pragma unroll
            for (int half = 0; half < 2; half++) {
                int row = row0 + half * 8;
                float v0 = acc[mt][nt][half * 2 + 0];
                float v1 = acc[mt][nt][half * 2 + 1];
                if (proj_mode) {
                    int b2 = row / SEQ, s2 = row % SEQ;
                    int hh = col / HD, d = col % HD;
                    float* dst = Y + ((size_t)((b2 * NH + hh) * SEQ + s2)) * HD + d;
                    dst[0] = v0; dst[1] = v1;
                } else {
                    float* dst = Y + (size_t)row * D_MODEL + col;
                    dst[0] = v0; dst[1] = v1;
                }
            }
        }
    }
}

// ============================================================================
// Causal flash attention, TF32 MMA. One block = 128 q-rows of one (b,h),
// 8 warps (warp w owns rows [16w,16w+16)), 64-row KV tiles.
// Q/K/P smem stride 68 (conflict-free A-pattern), V stride 72 (conflict-free
// k-major B-pattern). P is a private buffer -> only 2 syncthreads per KV iter.
// ============================================================================
#define QT 128
#define KT 64
#define QST 68
#define VST 72
#define FSMEM ((2*QT*QST + KT*QST + KT*VST) * 4)

__global__ __launch_bounds__(256, 2) void flash_kernel()
{
    extern __shared__ unsigned smf[];
    unsigned* Qs = smf;                 // QT x QST
    unsigned* Ks = Qs + QT * QST;       // KT x QST
    unsigned* Vs = Ks + KT * QST;       // KT x VST
    unsigned* Ps = Vs + KT * VST;       // QT x QST (warp-private rows)

    const int tid = threadIdx.x;
    const int w = tid >> 5, lane = tid & 31;
    const int g = lane >> 2, tq = lane & 3;
    const int bh = blockIdx.y;
    const int b = bh / NH, h = bh % NH;
    const int qt = (gridDim.x - 1 - blockIdx.x);   // heavy blocks first
    const int q0 = qt * QT;

    const float* qbase = g_q + (size_t)(b * NH + h) * SEQ * HD;
    const float* kbase = g_k + (size_t)(b * NH + h) * SEQ * HD;
    const float* vbase = g_v + (size_t)(b * NH + h) * SEQ * HD;

    // load Q tile (128x64), pre-scaled by 1/sqrt(HD)
    #pragma unroll
    for (int i = 0; i < 8; i++) {
        int idx = tid + i * 256;
        int r = idx >> 4, c4 = (idx & 15) << 2;
        float4 vq = *(const float4*)(qbase + (size_t)(q0 + r) * HD + c4);
        unsigned* dq = Qs + r * QST + c4;
        dq[0] = f2tf(vq.x * 0.125f); dq[1] = f2tf(vq.y * 0.125f);
        dq[2] = f2tf(vq.z * 0.125f); dq[3] = f2tf(vq.w * 0.125f);
    }

    float o[8][4];
    #pragma unroll
    for (int nt = 0; nt < 8; nt++)
        #pragma unroll
        for (int r = 0; r < 4; r++) o[nt][r] = 0.f;
    float m0 = -INFINITY, m1 = -INFINITY, l0 = 0.f, l1 = 0.f;

    const int prow = w * 16 + g;         // tile-local row of c0/c1
    const int row0g = q0 + prow;         // global seq row of c0/c1
    const int row1g = row0g + 8;         // global seq row of c2/c3

    const int ktiles = 2 * qt + 2;
    for (int kt = 0; kt < ktiles; kt++) {
        const int kv0 = kt * KT;
        // load K, V tiles (64x64 each)
        #pragma unroll
        for (int i = 0; i < 4; i++) {
            int idx = tid + i * 256;
            int r = idx >> 4, c4 = (idx & 15) << 2;
            float4 vk = *(const float4*)(kbase + (size_t)(kv0 + r) * HD + c4);
            unsigned* dk = Ks + r * QST + c4;
            dk[0] = f2tf(vk.x); dk[1] = f2tf(vk.y); dk[2] = f2tf(vk.z); dk[3] = f2tf(vk.w);
            float4 vv = *(const float4*)(vbase + (size_t)(kv0 + r) * HD + c4);
            unsigned* dv = Vs + r * VST + c4;
            dv[0] = f2tf(vv.x); dv[1] = f2tf(vv.y); dv[2] = f2tf(vv.z); dv[3] = f2tf(vv.w);
        }
        __syncthreads();

        // scores S = Q K^T (16 rows x 64 cols per warp)
        float sc[8][4];
        #pragma unroll
        for (int nt = 0; nt < 8; nt++)
            #pragma unroll
            for (int r = 0; r < 4; r++) sc[nt][r] = 0.f;
        #pragma unroll
        for (int kk = 0; kk < HD; kk += 8) {
            unsigned af[4];
            af[0] = Qs[prow * QST + kk + tq];
            af[1] = Qs[(prow + 8) * QST + kk + tq];
            af[2] = Qs[prow * QST + kk + tq + 4];
            af[3] = Qs[(prow + 8) * QST + kk + tq + 4];
            #pragma unroll
            for (int nt = 0; nt < 8; nt++) {
                unsigned bf[2];
                int col = nt * 8 + g;
                bf[0] = Ks[col * QST + kk + tq];
                bf[1] = Ks[col * QST + kk + tq + 4];
                mma8(sc[nt], af, bf);
            }
        }

        // causal mask (needed only when this KV tile can exceed the row)
        const bool msk0 = (kv0 + KT - 1 > row0g);
        const bool msk1 = (kv0 + KT - 1 > row1g);
        if (msk0 | msk1) {
            #pragma unroll
            for (int nt = 0; nt < 8; nt++) {
                int c0 = kv0 + nt * 8 + tq * 2;
                if (msk0) {
                    if (c0     > row0g) sc[nt][0] = -1e30f;
                    if (c0 + 1 > row0g) sc[nt][1] = -1e30f;
                }
                if (msk1) {
                    if (c0     > row1g) sc[nt][2] = -1e30f;
                    if (c0 + 1 > row1g) sc[nt][3] = -1e30f;
                }
            }
        }

        // online softmax
        float rm0 = -1e30f, rm1 = -1e30f;
        #pragma unroll
        for (int nt = 0; nt < 8; nt++) {
            rm0 = fmaxf(rm0, fmaxf(sc[nt][0], sc[nt][1]));
            rm1 = fmaxf(rm1, fmaxf(sc[nt][2], sc[nt][3]));
        }
        rm0 = fmaxf(rm0, __shfl_xor_sync(0xffffffffu, rm0, 1));
        rm0 = fmaxf(rm0, __shfl_xor_sync(0xffffffffu, rm0, 2));
        rm1 = fmaxf(rm1, __shfl_xor_sync(0xffffffffu, rm1, 1));
        rm1 = fmaxf(rm1, __shfl_xor_sync(0xffffffffu, rm1, 2));

        float nm0 = fmaxf(m0, rm0), nm1 = fmaxf(m1, rm1);
        float a0 = __expf(m0 - nm0), a1 = __expf(m1 - nm1);
        m0 = nm0; m1 = nm1;

        float rs0 = 0.f, rs1 = 0.f;
        #pragma unroll
        for (int nt = 0; nt < 8; nt++) {
            float p0 = __expf(sc[nt][0] - nm0); sc[nt][0] = p0; rs0 += p0;
            float p1 = __expf(sc[nt][1] - nm0); sc[nt][1] = p1; rs0 += p1;
            float p2 = __expf(sc[nt][2] - nm1); sc[nt][2] = p2; rs1 += p2;
            float p3 = __expf(sc[nt][3] - nm1); sc[nt][3] = p3; rs1 += p3;
        }
        rs0 += __shfl_xor_sync(0xffffffffu, rs0, 1);
        rs0 += __shfl_xor_sync(0xffffffffu, rs0, 2);
        rs1 += __shfl_xor_sync(0xffffffffu, rs1, 1);
        rs1 += __shfl_xor_sync(0xffffffffu, rs1, 2);
        l0 = l0 * a0 + rs0;
        l1 = l1 * a1 + rs1;

        #pragma unroll
        for (int nt = 0; nt < 8; nt++) {
            o[nt][0] *= a0; o[nt][1] *= a0;
            o[nt][2] *= a1; o[nt][3] *= a1;
        }

        // write P into the warp-private rows of Ps (no block sync needed)
        #pragma unroll
        for (int nt = 0; nt < 8; nt++) {
            int c = nt * 8 + tq * 2;
            Ps[prow * QST + c]           = f2tf(sc[nt][0]);
            Ps[prow * QST + c + 1]       = f2tf(sc[nt][1]);
            Ps[(prow + 8) * QST + c]     = f2tf(sc[nt][2]);
            Ps[(prow + 8) * QST + c + 1] = f2tf(sc[nt][3]);
        }
        __syncwarp();

        // O += P V
        #pragma unroll
        for (int kk = 0; kk < KT; kk += 8) {
            unsigned af[4];
            af[0] = Ps[prow * QST + kk + tq];
            af[1] = Ps[(prow + 8) * QST + kk + tq];
            af[2] = Ps[prow * QST + kk + tq + 4];
            af[3] = Ps[(prow + 8) * QST + kk + tq + 4];
            #pragma unroll
            for (int nt = 0; nt < 8; nt++) {
                unsigned bf[2];
                int col = nt * 8 + g;
                bf[0] = Vs[(kk + tq) * VST + col];
                bf[1] = Vs[(kk + tq + 4) * VST + col];
                mma8(o[nt], af, bf);
            }
        }
        __syncthreads();   // protect Ks/Vs before next iteration's stores
    }

    // epilogue: normalize, write ctx[b*S + row][h*64 + d]
    float inv0 = 1.f / l0, inv1 = 1.f / l1;
    #pragma unroll
    for (int nt = 0; nt < 8; nt++) {
        int colg = h * HD + nt * 8 + tq * 2;
        size_t r0 = (size_t)(b * SEQ + row0g) * D_MODEL + colg;
        size_t r1 = (size_t)(b * SEQ + row1g) * D_MODEL + colg;
        g_ctx[r0]     = o[nt][0] * inv0;
        g_ctx[r0 + 1] = o[nt][1] * inv0;
        g_ctx[r1]     = o[nt][2] * inv1;
        g_ctx[r1 + 1] = o[nt][3] * inv1;
    }
}

// ============================================================================
extern "C" void kernel_launch(void* const* d_in, const int* in_sizes, int n_in,
                              void* d_out, int out_size)
{
    const float* x  = (const float*)d_in[0];
    const float* qW = (const float*)d_in[1];
    const float* kW = (const float*)d_in[2];
    const float* vW = (const float*)d_in[3];
    const float* oW = (const float*)d_in[4];
    float* out = (float*)d_out;

    float *pq, *pk, *pv, *pctx;
    cudaGetSymbolAddress((void**)&pq, g_q);
    cudaGetSymbolAddress((void**)&pk, g_k);
    cudaGetSymbolAddress((void**)&pv, g_v);
    cudaGetSymbolAddress((void**)&pctx, g_ctx);

    cudaFuncSetAttribute(gemm_tf32, cudaFuncAttributeMaxDynamicSharedMemorySize, GSMEM);
    cudaFuncSetAttribute(flash_kernel, cudaFuncAttributeMaxDynamicSharedMemorySize, FSMEM);

    dim3 ggrid(D_MODEL / GBN, MROWS / GBM);   // (8, 32)
    gemm_tf32<<<ggrid, 256, GSMEM>>>(x, qW, pq, 1);
    gemm_tf32<<<ggrid, 256, GSMEM>>>(x, kW, pk, 1);
    gemm_tf32<<<ggrid, 256, GSMEM>>>(x, vW, pv, 1);

    flash_kernel<<<dim3(SEQ / QT, BATCH * NH), 256, FSMEM>>>();

    gemm_tf32<<<ggrid, 256, GSMEM>>>(pctx, oW, out, 0);
}